// round 8
// baseline (speedup 1.0000x reference)
#include <cuda_runtime.h>
#include <cuda_bf16.h>
#include <math.h>
#include <stdint.h>

// ---------------------------------------------------------------------------
// Problem constants: B=4, S=2048, D=1024, H=16, HD=64; rows = B*S = 8192
// ---------------------------------------------------------------------------
#define ROWS 8192
#define DMODEL 1024
#define NHEAD 16
#define HDIM 64
#define SEQ 2048

typedef __nv_bfloat16 bf16;

// Scratch (device globals: allocation-free rule)
__device__ float g_qkv[ROWS * 3 * DMODEL];          // fp32 QKV for attention
__device__ bf16  g_lnh[ROWS * DMODEL];              // LN output split
__device__ bf16  g_lnl[ROWS * DMODEL];
__device__ bf16  g_ctxh[ROWS * DMODEL];             // attention ctx split
__device__ bf16  g_ctxl[ROWS * DMODEL];
__device__ bf16  g_hidh[ROWS * 4 * DMODEL];         // MLP hidden split
__device__ bf16  g_hidl[ROWS * 4 * DMODEL];
// Weight splits, stored TRANSPOSED [N][K] for col-major B fragments
__device__ bf16  g_wqh[3 * DMODEL * DMODEL];
__device__ bf16  g_wql[3 * DMODEL * DMODEL];
__device__ bf16  g_woh[DMODEL * DMODEL];
__device__ bf16  g_wol[DMODEL * DMODEL];
__device__ bf16  g_w1h[4 * DMODEL * DMODEL];
__device__ bf16  g_w1l[4 * DMODEL * DMODEL];
__device__ bf16  g_w2h[DMODEL * 4 * DMODEL];
__device__ bf16  g_w2l[DMODEL * 4 * DMODEL];

// ---------------------------------------------------------------------------
// Small helpers
// ---------------------------------------------------------------------------
typedef unsigned long long u64t;

__device__ __forceinline__ uint32_t smem_u32(const void* p) {
    uint32_t a;
    asm("{ .reg .u64 t; cvta.to.shared.u64 t, %1; cvt.u32.u64 %0, t; }"
        : "=r"(a) : "l"(p));
    return a;
}
__device__ __forceinline__ void cp16(uint32_t s, const void* g) {
    asm volatile("cp.async.cg.shared.global [%0], [%1], 16;" :: "r"(s), "l"(g));
}
__device__ __forceinline__ void cp_commit() {
    asm volatile("cp.async.commit_group;" ::: "memory");
}
__device__ __forceinline__ void ldsm_x4(uint32_t a,
    unsigned& r0, unsigned& r1, unsigned& r2, unsigned& r3) {
    asm volatile("ldmatrix.sync.aligned.m8n8.x4.shared.b16 {%0,%1,%2,%3}, [%4];"
        : "=r"(r0), "=r"(r1), "=r"(r2), "=r"(r3) : "r"(a));
}
__device__ __forceinline__ void ldsm_x2(uint32_t a, unsigned& r0, unsigned& r1) {
    asm volatile("ldmatrix.sync.aligned.m8n8.x2.shared.b16 {%0,%1}, [%2];"
        : "=r"(r0), "=r"(r1) : "r"(a));
}

__device__ __forceinline__ void mma_bf16(float* c,
    unsigned a0, unsigned a1, unsigned a2, unsigned a3,
    unsigned b0, unsigned b1)
{
    asm volatile(
        "mma.sync.aligned.m16n8k16.row.col.f32.bf16.bf16.f32 "
        "{%0,%1,%2,%3},{%4,%5,%6,%7},{%8,%9},{%0,%1,%2,%3};"
        : "+f"(c[0]), "+f"(c[1]), "+f"(c[2]), "+f"(c[3])
        : "r"(a0), "r"(a1), "r"(a2), "r"(a3), "r"(b0), "r"(b1));
}

// Split a float into bf16 hi + bf16 lo (v ~= hi + lo, residual ~2^-17 * |v|)
__device__ __forceinline__ void split1(float v, bf16& h, bf16& l) {
    h = __float2bfloat16(v);
    l = __float2bfloat16(v - __bfloat162float(h));
}
// Pack two bf16 into a 32-bit word
__device__ __forceinline__ unsigned packbf2(bf16 a, bf16 b) {
    __nv_bfloat162 p = __halves2bfloat162(a, b);
    unsigned u; __builtin_memcpy(&u, &p, 4); return u;
}

__device__ __forceinline__ float gelu_tanh_f(float x) {
    const float c = 0.7978845608028654f;  // sqrt(2/pi)
    float t = tanhf(c * (x + 0.044715f * x * x * x));
    return 0.5f * x * (1.0f + t);
}

// f32x2 packed helpers for the flash kernel
__device__ __forceinline__ u64t f2pack(float a, float b) {
    u64t r; asm("mov.b64 %0,{%1,%2};" : "=l"(r) : "f"(a), "f"(b)); return r;
}
__device__ __forceinline__ void f2unpack(u64t v, float& a, float& b) {
    asm("mov.b64 {%0,%1},%2;" : "=f"(a), "=f"(b) : "l"(v));
}
__device__ __forceinline__ u64t ffma2(u64t a, u64t b, u64t c) {
    u64t d; asm("fma.rn.f32x2 %0,%1,%2,%3;" : "=l"(d) : "l"(a), "l"(b), "l"(c)); return d;
}
__device__ __forceinline__ u64t fmul2(u64t a, u64t b) {
    u64t d; asm("mul.rn.f32x2 %0,%1,%2;" : "=l"(d) : "l"(a), "l"(b)); return d;
}

// ---------------------------------------------------------------------------
// Weight transpose + split: W[K][N] fp32 -> Wh,Wl [N][K] bf16
// block (32,8), grid (N/32, K/32)
// ---------------------------------------------------------------------------
__global__ __launch_bounds__(256) void wsplit_kernel(
    const float* __restrict__ W, bf16* __restrict__ Wh, bf16* __restrict__ Wl,
    int K, int N)
{
    __shared__ float t[32][33];
    int n0 = blockIdx.x * 32, k0 = blockIdx.y * 32;
    int tx = threadIdx.x, ty = threadIdx.y;
    #pragma unroll
    for (int i = ty; i < 32; i += 8)
        t[i][tx] = W[(size_t)(k0 + i) * N + n0 + tx];
    __syncthreads();
    #pragma unroll
    for (int i = ty; i < 32; i += 8) {
        float v = t[tx][i];                   // = W[k0+tx][n0+i]
        bf16 h, l; split1(v, h, l);
        size_t o = (size_t)(n0 + i) * K + k0 + tx;
        Wh[o] = h; Wl[o] = l;
    }
}

// ---------------------------------------------------------------------------
// LayerNorm + split: one block per row, 256 threads, writes bf16 hi/lo
// ---------------------------------------------------------------------------
__global__ __launch_bounds__(256) void ln_split_kernel(
    const float* __restrict__ x, const float* __restrict__ g,
    const float* __restrict__ sft, bf16* __restrict__ oh, bf16* __restrict__ ol)
{
    __shared__ float red[16];
    int row = blockIdx.x;
    int t = threadIdx.x;
    float4 v = ((const float4*)(x + (size_t)row * DMODEL))[t];
    float s = v.x + v.y + v.z + v.w;
    float q = v.x * v.x + v.y * v.y + v.z * v.z + v.w * v.w;
    #pragma unroll
    for (int o = 16; o; o >>= 1) {
        s += __shfl_xor_sync(0xffffffffu, s, o);
        q += __shfl_xor_sync(0xffffffffu, q, o);
    }
    if ((t & 31) == 0) { red[t >> 5] = s; red[8 + (t >> 5)] = q; }
    __syncthreads();
    s = 0.f; q = 0.f;
    #pragma unroll
    for (int i = 0; i < 8; i++) { s += red[i]; q += red[8 + i]; }
    float mean = s * (1.0f / DMODEL);
    float var  = q * (1.0f / DMODEL) - mean * mean;
    float inv  = rsqrtf(var + 1e-5f);
    float4 gv = ((const float4*)g)[t];
    float4 sv = ((const float4*)sft)[t];
    float o0 = gv.x * (v.x - mean) * inv + sv.x;
    float o1 = gv.y * (v.y - mean) * inv + sv.y;
    float o2 = gv.z * (v.z - mean) * inv + sv.z;
    float o3 = gv.w * (v.w - mean) * inv + sv.w;
    bf16 h0,h1,h2,h3,l0,l1,l2,l3;
    split1(o0,h0,l0); split1(o1,h1,l1); split1(o2,h2,l2); split1(o3,h3,l3);
    size_t idx = (size_t)row * DMODEL + t * 4;
    *(uint2*)(oh + idx) = make_uint2(packbf2(h0,h1), packbf2(h2,h3));
    *(uint2*)(ol + idx) = make_uint2(packbf2(l0,l1), packbf2(l2,l3));
}

// ---------------------------------------------------------------------------
// Split-bf16 HMMA GEMM:  C[M,N] = epi( (Ah+Al)[M,K] @ (Wh+Wl)^T[N,K]^T )
// computed as Ah@Wh + Ah@Wl + Al@Wh  (3 bf16 MMAs, fp32 accumulate)
// Tiles: 128x128x32, 256 threads = 8 warps (2 M x 4 N), 64x32 per warp.
// Fragments loaded via ldmatrix (stride-40 rows: conflict-free LDSM).
// EPI bits: 1=bias, 2=residual, 4=gelu. SPLITOUT: write bf16 hi/lo arrays.
// NOTE: res and C may ALIAS (FC2 writes in-place onto its residual input),
// so they are deliberately NOT __restrict__.
// ---------------------------------------------------------------------------
#define GBM 128
#define GBN 128
#define GBK 32
#define SST 40                     // smem row stride in bf16 units
#define TILE_B (GBM * SST * 2)     // 10240 bytes per tile array
#define OFF_AH 0
#define OFF_AL (1 * TILE_B)
#define OFF_BH (2 * TILE_B)
#define OFF_BL (3 * TILE_B)
#define BUF_B  (4 * TILE_B)        // 40960
#define GSMEM  (2 * BUF_B)         // 81920

template <int EPI, bool SPLITOUT>
__global__ __launch_bounds__(256, 2) void hgemm_k(
    const bf16* __restrict__ Ah, const bf16* __restrict__ Al,
    const bf16* __restrict__ Wh, const bf16* __restrict__ Wl,
    const float* __restrict__ bias, const float* res,
    float* C, bf16* __restrict__ Ch, bf16* __restrict__ Cl,
    int M, int N, int K)
{
    extern __shared__ __align__(16) unsigned char dsm[];
    uint32_t sb = smem_u32(dsm);

    int tid = threadIdx.x;
    int lane = tid & 31, wid = tid >> 5;
    int wm = wid >> 2, wn = wid & 3;       // warp grid 2 x 4
    int g = lane >> 2, t4 = lane & 3;
    int row0 = blockIdx.y * GBM;
    int col0 = blockIdx.x * GBN;

    float acc[4][4][4];
    #pragma unroll
    for (int i = 0; i < 4; i++)
        #pragma unroll
        for (int j = 0; j < 4; j++)
            #pragma unroll
            for (int k = 0; k < 4; k++) acc[i][j][k] = 0.f;

    // ldmatrix lane->address components (within a k-slice)
    // A x4: lanes 0-15 -> rows 0-15 byte +0 (m0,m1); 16-31 -> rows 0-15 byte +16 (m2,m3)
    int a_lrow = lane & 15;
    int a_lcol = (lane >> 4) * 16;
    // B x2: lanes 0-7 -> rows byte +0 (m0); 8-15 -> rows byte +16 (m1)
    int b_lrow = lane & 7;
    int b_lcol = ((lane >> 3) & 1) * 16;

    // ---- async tile loader: 128 rows x 32 k bf16 per array, 16B chunks ----
    auto load_tiles = [&](int buf, int k0) {
        uint32_t base = sb + buf * BUF_B;
        #pragma unroll
        for (int it = 0; it < 2; it++) {
            int slot = it * 256 + tid;
            int r = slot >> 2, c = slot & 3;
            uint32_t soff = (uint32_t)(r * SST + c * 8) * 2;
            size_t aoff = (size_t)(row0 + r) * K + k0 + c * 8;
            size_t boff = (size_t)(col0 + r) * K + k0 + c * 8;
            cp16(base + OFF_AH + soff, Ah + aoff);
            cp16(base + OFF_AL + soff, Al + aoff);
            cp16(base + OFF_BH + soff, Wh + boff);
            cp16(base + OFF_BL + soff, Wl + boff);
        }
    };

    load_tiles(0, 0);
    cp_commit();

    int buf = 0;
    for (int k0 = 0; k0 < K; k0 += GBK) {
        bool has_next = (k0 + GBK) < K;
        __syncthreads();                       // everyone done reading buf^1
        if (has_next) { load_tiles(buf ^ 1, k0 + GBK); cp_commit(); }
        if (has_next) asm volatile("cp.async.wait_group 1;" ::: "memory");
        else          asm volatile("cp.async.wait_group 0;" ::: "memory");
        __syncthreads();                       // all threads' data visible

        uint32_t ab = sb + buf * BUF_B;
        #pragma unroll
        for (int ks = 0; ks < 2; ks++) {
            int kob = ks * 32;                 // byte offset of k-slice
            // --- B fragments via ldmatrix.x2 (hi and lo) ---
            unsigned bh[4][2], bl[4][2];
            #pragma unroll
            for (int nt = 0; nt < 4; nt++) {
                int n = wn * 32 + nt * 8 + b_lrow;
                uint32_t a = ab + OFF_BH + (uint32_t)(n * SST * 2 + kob + b_lcol);
                ldsm_x2(a, bh[nt][0], bh[nt][1]);
                ldsm_x2(a + (OFF_BL - OFF_BH), bl[nt][0], bl[nt][1]);
            }
            // --- A fragments via ldmatrix.x4 (hi and lo), then 3-term MMA ---
            #pragma unroll
            for (int mt = 0; mt < 4; mt++) {
                int r = wm * 64 + mt * 16 + a_lrow;
                uint32_t a = ab + OFF_AH + (uint32_t)(r * SST * 2 + kob + a_lcol);
                unsigned ah0, ah1, ah2, ah3, al0, al1, al2, al3;
                ldsm_x4(a, ah0, ah1, ah2, ah3);
                ldsm_x4(a + (OFF_AL - OFF_AH), al0, al1, al2, al3);
                #pragma unroll
                for (int nt = 0; nt < 4; nt++) {
                    mma_bf16(acc[mt][nt], ah0, ah1, ah2, ah3, bh[nt][0], bh[nt][1]);
                    mma_bf16(acc[mt][nt], ah0, ah1, ah2, ah3, bl[nt][0], bl[nt][1]);
                    mma_bf16(acc[mt][nt], al0, al1, al2, al3, bh[nt][0], bh[nt][1]);
                }
            }
        }
        buf ^= 1;
    }

    // ---- epilogue ----
    #pragma unroll
    for (int mt = 0; mt < 4; mt++) {
        #pragma unroll
        for (int nt = 0; nt < 4; nt++) {
            int c = col0 + wn * 32 + nt * 8 + 2 * t4;
            #pragma unroll
            for (int half = 0; half < 2; half++) {
                int r = row0 + wm * 64 + mt * 16 + g + half * 8;
                float v0 = acc[mt][nt][half * 2 + 0];
                float v1 = acc[mt][nt][half * 2 + 1];
                if (EPI & 1) {
                    float2 bb = *(const float2*)(bias + c);
                    v0 += bb.x; v1 += bb.y;
                }
                if (EPI & 4) { v0 = gelu_tanh_f(v0); v1 = gelu_tanh_f(v1); }
                if (EPI & 2) {
                    float2 rr = *(const float2*)(res + (size_t)r * N + c);
                    v0 += rr.x; v1 += rr.y;
                }
                if (SPLITOUT) {
                    bf16 h0, l0, h1, l1;
                    split1(v0, h0, l0); split1(v1, h1, l1);
                    *(unsigned*)(Ch + (size_t)r * N + c) = packbf2(h0, h1);
                    *(unsigned*)(Cl + (size_t)r * N + c) = packbf2(l0, l1);
                } else {
                    *(float2*)(C + (size_t)r * N + c) = make_float2(v0, v1);
                }
            }
        }
    }
}

// ---------------------------------------------------------------------------
// Flash attention (causal), fp32 f32x2 inner loops. 64x64 tiles, HD=64.
// qkv layout: [ROWS, 3*D]; q at col h*64, k at D+h*64, v at 2D+h*64
// Writes ctx SPLIT to bf16 hi/lo arrays [ROWS][D].
// Separate K and V buffers: K+V loaded together (batched MLP), 3 barriers/iter.
// smem: Qs[64][68] + Ks[64][68] + Vs[64][68] + Ps[64][65] = 68864 B dynamic
// ---------------------------------------------------------------------------
#define QS_STRIDE 68
#define PS_STRIDE 65
#define FLASH_SMEM ((64 * QS_STRIDE * 3 + 64 * PS_STRIDE) * 4)

__global__ __launch_bounds__(256) void flash_kernel(
    const float* __restrict__ qkv, bf16* __restrict__ ctxh, bf16* __restrict__ ctxl)
{
    extern __shared__ float sm[];
    float* Qs = sm;
    float* Ks = sm + 64 * QS_STRIDE;
    float* Vs = sm + 2 * 64 * QS_STRIDE;
    float* Ps = sm + 3 * 64 * QS_STRIDE;

    int tid = threadIdx.x;
    int tx = tid & 15;
    int ty = tid >> 4;
    int bh = blockIdx.y;
    int b = bh >> 4, h = bh & 15;
    int qt = (int)gridDim.x - 1 - (int)blockIdx.x;  // heavy tiles first
    int qbase = qt * 64;

    const float* Qp = qkv + (size_t)(b * SEQ) * (3 * DMODEL) + h * HDIM;
    const float* Kp = Qp + DMODEL;
    const float* Vp = Qp + 2 * DMODEL;

    #pragma unroll
    for (int m = 0; m < 4; m++) {
        int lin = tid + m * 256;
        int r = lin >> 4, dv = lin & 15;
        float4 q = *(const float4*)(Qp + (size_t)(qbase + r) * (3 * DMODEL) + dv * 4);
        q.x *= 0.125f; q.y *= 0.125f; q.z *= 0.125f; q.w *= 0.125f;
        *(float4*)&Qs[r * QS_STRIDE + dv * 4] = q;
    }

    u64t o2[4][2];
    #pragma unroll
    for (int i = 0; i < 4; i++) { o2[i][0] = 0ull; o2[i][1] = 0ull; }
    float mrow[4] = {-1e30f, -1e30f, -1e30f, -1e30f};
    float lrow[4] = {0.f, 0.f, 0.f, 0.f};

    for (int kt = 0; kt <= qt; kt++) {
        int kb = kt * 64;
        __syncthreads();   // prev-iter reads of Ks/Vs/Ps done; Q visible on 1st
        // Batched K + V loads (8 independent float4 LDGs in flight)
        #pragma unroll
        for (int m = 0; m < 4; m++) {
            int lin = tid + m * 256;
            int r = lin >> 4, dv = lin & 15;
            size_t row_off = (size_t)(kb + r) * (3 * DMODEL) + dv * 4;
            float4 kv = *(const float4*)(Kp + row_off);
            float4 vv = *(const float4*)(Vp + row_off);
            *(float4*)&Ks[r * QS_STRIDE + dv * 4] = kv;
            *(float4*)&Vs[r * QS_STRIDE + dv * 4] = vv;
        }
        __syncthreads();

        // Scores (packed over d pairs)
        u64t s2[4][4];
        #pragma unroll
        for (int i = 0; i < 4; i++)
            #pragma unroll
            for (int j = 0; j < 4; j++) s2[i][j] = 0ull;
        #pragma unroll 4
        for (int d4 = 0; d4 < 16; d4++) {
            ulonglong2 qv[4], kv[4];
            #pragma unroll
            for (int i = 0; i < 4; i++)
                qv[i] = *(const ulonglong2*)&Qs[(ty * 4 + i) * QS_STRIDE + d4 * 4];
            #pragma unroll
            for (int j = 0; j < 4; j++)
                kv[j] = *(const ulonglong2*)&Ks[(tx * 4 + j) * QS_STRIDE + d4 * 4];
            #pragma unroll
            for (int i = 0; i < 4; i++)
                #pragma unroll
                for (int j = 0; j < 4; j++) {
                    s2[i][j] = ffma2(qv[i].x, kv[j].x, s2[i][j]);
                    s2[i][j] = ffma2(qv[i].y, kv[j].y, s2[i][j]);
                }
        }
        float s[4][4];
        #pragma unroll
        for (int i = 0; i < 4; i++)
            #pragma unroll
            for (int j = 0; j < 4; j++) {
                float lo, hi; f2unpack(s2[i][j], lo, hi);
                s[i][j] = lo + hi;
            }

        if (kt == qt) {
            #pragma unroll
            for (int i = 0; i < 4; i++)
                #pragma unroll
                for (int j = 0; j < 4; j++)
                    if (tx * 4 + j > ty * 4 + i) s[i][j] = -1e30f;
        }

        // Online softmax (row stats across 16 lanes per row)
        #pragma unroll
        for (int i = 0; i < 4; i++) {
            float mx = fmaxf(fmaxf(s[i][0], s[i][1]), fmaxf(s[i][2], s[i][3]));
            #pragma unroll
            for (int off = 8; off; off >>= 1)
                mx = fmaxf(mx, __shfl_xor_sync(0xffffffffu, mx, off, 16));
            float mnew = fmaxf(mrow[i], mx);
            float alpha = __expf(mrow[i] - mnew);
            mrow[i] = mnew;
            float ls = 0.f;
            #pragma unroll
            for (int j = 0; j < 4; j++) {
                float p = __expf(s[i][j] - mnew);
                Ps[(ty * 4 + i) * PS_STRIDE + tx * 4 + j] = p;
                ls += p;
            }
            #pragma unroll
            for (int off = 8; off; off >>= 1)
                ls += __shfl_xor_sync(0xffffffffu, ls, off, 16);
            lrow[i] = lrow[i] * alpha + ls;
            u64t ap = f2pack(alpha, alpha);
            o2[i][0] = fmul2(o2[i][0], ap);
            o2[i][1] = fmul2(o2[i][1], ap);
        }

        __syncthreads();   // Ps visible to all lanes before PV

        // O += P @ V (packed over output cols)
        #pragma unroll 8
        for (int k = 0; k < 64; k++) {
            ulonglong2 v2 = *(const ulonglong2*)&Vs[k * QS_STRIDE + tx * 4];
            #pragma unroll
            for (int i = 0; i < 4; i++) {
                float p = Ps[(ty * 4 + i) * PS_STRIDE + k];
                u64t pp = f2pack(p, p);
                o2[i][0] = ffma2(pp, v2.x, o2[i][0]);
                o2[i][1] = ffma2(pp, v2.y, o2[i][1]);
            }
        }
    }

    #pragma unroll
    for (int i = 0; i < 4; i++) {
        int r = qbase + ty * 4 + i;
        float inv = 1.0f / lrow[i];
        float o0, o1, o2f, o3;
        f2unpack(o2[i][0], o0, o1);
        f2unpack(o2[i][1], o2f, o3);
        o0 *= inv; o1 *= inv; o2f *= inv; o3 *= inv;
        bf16 h0,h1,h2,h3,l0,l1,l2,l3;
        split1(o0,h0,l0); split1(o1,h1,l1); split1(o2f,h2,l2); split1(o3,h3,l3);
        size_t idx = (size_t)(b * SEQ + r) * DMODEL + h * HDIM + tx * 4;
        *(uint2*)(ctxh + idx) = make_uint2(packbf2(h0,h1), packbf2(h2,h3));
        *(uint2*)(ctxl + idx) = make_uint2(packbf2(l0,l1), packbf2(l2,l3));
    }
}

// ---------------------------------------------------------------------------
// Host launcher. Inputs: x, Wqkv, Wout, bout, W1, b1, W2, b2, g1, s1, g2, s2
// ---------------------------------------------------------------------------
extern "C" void kernel_launch(void* const* d_in, const int* in_sizes, int n_in,
                              void* d_out, int out_size)
{
    (void)in_sizes; (void)n_in; (void)out_size;
    const float* x    = (const float*)d_in[0];
    const float* Wqkv = (const float*)d_in[1];
    const float* Wout = (const float*)d_in[2];
    const float* bout = (const float*)d_in[3];
    const float* W1   = (const float*)d_in[4];
    const float* b1   = (const float*)d_in[5];
    const float* W2   = (const float*)d_in[6];
    const float* b2   = (const float*)d_in[7];
    const float* g1   = (const float*)d_in[8];
    const float* s1   = (const float*)d_in[9];
    const float* g2   = (const float*)d_in[10];
    const float* s2   = (const float*)d_in[11];
    float* out = (float*)d_out;

    float* qkv;  bf16 *lnh, *lnl, *ctxh, *ctxl, *hidh, *hidl;
    bf16 *wqh, *wql, *woh, *wol, *w1h, *w1l, *w2h, *w2l;
    cudaGetSymbolAddress((void**)&qkv,  g_qkv);
    cudaGetSymbolAddress((void**)&lnh,  g_lnh);
    cudaGetSymbolAddress((void**)&lnl,  g_lnl);
    cudaGetSymbolAddress((void**)&ctxh, g_ctxh);
    cudaGetSymbolAddress((void**)&ctxl, g_ctxl);
    cudaGetSymbolAddress((void**)&hidh, g_hidh);
    cudaGetSymbolAddress((void**)&hidl, g_hidl);
    cudaGetSymbolAddress((void**)&wqh,  g_wqh);
    cudaGetSymbolAddress((void**)&wql,  g_wql);
    cudaGetSymbolAddress((void**)&woh,  g_woh);
    cudaGetSymbolAddress((void**)&wol,  g_wol);
    cudaGetSymbolAddress((void**)&w1h,  g_w1h);
    cudaGetSymbolAddress((void**)&w1l,  g_w1l);
    cudaGetSymbolAddress((void**)&w2h,  g_w2h);
    cudaGetSymbolAddress((void**)&w2l,  g_w2l);

    cudaFuncSetAttribute(flash_kernel,
        cudaFuncAttributeMaxDynamicSharedMemorySize, FLASH_SMEM);
    cudaFuncSetAttribute(hgemm_k<0, false>,
        cudaFuncAttributeMaxDynamicSharedMemorySize, GSMEM);
    cudaFuncSetAttribute(hgemm_k<3, false>,
        cudaFuncAttributeMaxDynamicSharedMemorySize, GSMEM);
    cudaFuncSetAttribute(hgemm_k<5, true>,
        cudaFuncAttributeMaxDynamicSharedMemorySize, GSMEM);

    // 0. Weight transpose + split (recomputed each call; ~20us total)
    wsplit_kernel<<<dim3(3 * DMODEL / 32, DMODEL / 32), dim3(32, 8)>>>(
        Wqkv, wqh, wql, DMODEL, 3 * DMODEL);
    wsplit_kernel<<<dim3(DMODEL / 32, DMODEL / 32), dim3(32, 8)>>>(
        Wout, woh, wol, DMODEL, DMODEL);
    wsplit_kernel<<<dim3(4 * DMODEL / 32, DMODEL / 32), dim3(32, 8)>>>(
        W1, w1h, w1l, DMODEL, 4 * DMODEL);
    wsplit_kernel<<<dim3(DMODEL / 32, 4 * DMODEL / 32), dim3(32, 8)>>>(
        W2, w2h, w2l, 4 * DMODEL, DMODEL);

    // 1. LN1 -> split
    ln_split_kernel<<<ROWS, 256>>>(x, g1, s1, lnh, lnl);
    // 2. QKV projection -> fp32 qkv
    hgemm_k<0, false><<<dim3(3 * DMODEL / GBN, ROWS / GBM), 256, GSMEM>>>(
        lnh, lnl, wqh, wql, nullptr, nullptr, qkv, nullptr, nullptr,
        ROWS, 3 * DMODEL, DMODEL);
    // 3. Flash attention -> ctx split
    flash_kernel<<<dim3(SEQ / 64, 4 * NHEAD), 256, FLASH_SMEM>>>(qkv, ctxh, ctxl);
    // 4. Out proj + bias + residual -> out fp32
    hgemm_k<3, false><<<dim3(DMODEL / GBN, ROWS / GBM), 256, GSMEM>>>(
        ctxh, ctxl, woh, wol, bout, x, out, nullptr, nullptr,
        ROWS, DMODEL, DMODEL);
    // 5. LN2 -> split
    ln_split_kernel<<<ROWS, 256>>>(out, g2, s2, lnh, lnl);
    // 6. FC1 + bias + GELU -> hidden split
    hgemm_k<5, true><<<dim3(4 * DMODEL / GBN, ROWS / GBM), 256, GSMEM>>>(
        lnh, lnl, w1h, w1l, b1, nullptr, nullptr, hidh, hidl,
        ROWS, 4 * DMODEL, DMODEL);
    // 7. FC2 + bias + residual -> out fp32 (res aliases C; handled in-kernel)
    hgemm_k<3, false><<<dim3(DMODEL / GBN, ROWS / GBM), 256, GSMEM>>>(
        hidh, hidl, w2h, w2l, b2, out, out, nullptr, nullptr,
        ROWS, DMODEL, 4 * DMODEL);
}